// round 3
// baseline (speedup 1.0000x reference)
#include <cuda_runtime.h>

#define T_STEPS 256
#define HU      64
#define G4      256
#define BBK2    16      // batch rows per block in main kernel
#define NTH     512
#define BATCH   4096

typedef unsigned long long u64;

// 1 GB scratch for xz = x@W1 + b1, layout [b][t][j] (j = gate column 0..255)
__device__ float XZbuf[(size_t)BATCH * T_STEPS * G4];

__device__ __forceinline__ u64 fma2(u64 a, u64 b, u64 c) {
    u64 d;
    asm("fma.rn.f32x2 %0, %1, %2, %3;" : "=l"(d) : "l"(a), "l"(b), "l"(c));
    return d;
}
__device__ __forceinline__ float hadd2(u64 v) {
    float l, h;
    asm("mov.b64 {%0, %1}, %2;" : "=f"(l), "=f"(h) : "l"(v));
    return l + h;
}
__device__ __forceinline__ float fexp(float x) {
    float y;
    asm("ex2.approx.f32 %0, %1;" : "=f"(y) : "f"(x * 1.4426950408889634f));
    return y;
}
__device__ __forceinline__ float frcp(float x) {
    float y;
    asm("rcp.approx.f32 %0, %1;" : "=f"(y) : "f"(x));
    return y;
}
__device__ __forceinline__ float sigf(float x)  { return frcp(1.0f + fexp(-x)); }
__device__ __forceinline__ float tanhfast(float x) {
    return fmaf(2.0f, frcp(1.0f + fexp(-2.0f * x)), -1.0f);
}

// ======================= K1: xz prepass ==========================
// xz[b][t][j] = b1[j] + sum_f x[b][t][f] * W1[f][j]
// Block: 256 threads (one per j), handles K1_BT (b,t) rows.
#define K1_BT 16

__global__ void __launch_bounds__(256)
k1_xz(const float* __restrict__ x, const float* __restrict__ W1,
      const float* __restrict__ b1)
{
    __shared__ __align__(16) float W1t[8 * 1024];   // k4-blocked transpose, 32KB
    __shared__ __align__(16) float xsh[K1_BT * 32];

    const int tid = threadIdx.x;
    const int j = tid;

    // load + transpose W1: src [k][j] -> dst (k>>2)*1024 + j*4 + (k&3)
    for (int i = tid; i < 32 * G4; i += 256) {
        int k = i >> 8, jj = i & 255;
        W1t[((k >> 2) << 10) + (jj << 2) + (k & 3)] = W1[i];
    }
    const long long bt0 = (long long)blockIdx.x * K1_BT;
    for (int i = tid; i < K1_BT * 32; i += 256)
        xsh[i] = x[bt0 * 32 + i];
    __syncthreads();

    const float bj = b1[j];
#pragma unroll 4
    for (int m = 0; m < K1_BT; m++) {
        u64 acc = 0ULL;
#pragma unroll
        for (int k4 = 0; k4 < 8; k4++) {
            ulonglong2 w  = *(const ulonglong2*)&W1t[(k4 << 10) + (j << 2)];
            ulonglong2 xv = *(const ulonglong2*)&xsh[m * 32 + (k4 << 2)];
            acc = fma2(xv.x, w.x, acc);
            acc = fma2(xv.y, w.y, acc);
        }
        XZbuf[(bt0 + m) * G4 + j] = hadd2(acc) + bj;
    }
}

// ======================= K2: fused recurrence ==========================
// smem layout (floats):
//   U1t  @ 0      (16384)   k4-blocked transpose [(k>>2)][j][k&3]
//   W2t  @ 16384  (16384)
//   U2t  @ 32768  (16384)
//   h1s  @ 49152  (2048)    [parity][16][64]
//   h2s  @ 51200  (2048)
//   zs   @ 53248  (4096)    [16][256]
#define SM_TOTAL_FLOATS 57344

__global__ void __launch_bounds__(NTH, 1)
k2_main(const float* __restrict__ U1, const float* __restrict__ W2,
        const float* __restrict__ U2, const float* __restrict__ b2,
        const float* __restrict__ Wd, const float* __restrict__ bd,
        const float* __restrict__ Wo, const float* __restrict__ bo,
        float* __restrict__ out)
{
    extern __shared__ __align__(16) float sm[];
    float* U1t = sm;
    float* W2t = sm + 16384;
    float* U2t = sm + 32768;
    float* h1s = sm + 49152;
    float* h2s = sm + 51200;
    float* zs  = sm + 53248;

    const int tid = threadIdx.x;

    // load + transpose recurrent weights
    for (int i = tid; i < HU * G4; i += NTH) {
        int k = i >> 8, j = i & 255;
        int d = ((k >> 2) << 10) + (j << 2) + (k & 3);
        float a = U1[i], b = W2[i], c = U2[i];
        U1t[d] = a; W2t[d] = b; U2t[d] = c;
    }
    for (int i = tid; i < 4096; i += NTH) { h1s[i] = 0.0f; h2s[i] = 0.0f; }

    // matvec role: gate column j, batch group pg (8 rows each)
    const int j  = tid & 255;
    const int pg = tid >> 8;
    const int bbase = pg * 8;
    // update role: unit uu, rows bq and bq+8
    const int uu = tid & 63;
    const int bq = tid >> 6;

    const float b2j = b2[j];
    float c1a = 0.0f, c1b = 0.0f, c2a = 0.0f, c2b = 0.0f;
    const int bglob0 = blockIdx.x * BBK2;

    __syncthreads();

    int cur = 0;
    for (int t = 0; t < T_STEPS; t++) {
        const int nxt = cur ^ 1;

        // prefetch xz for my 8 batch rows (DRAM latency hidden by phase 1)
        float xzv[8];
#pragma unroll
        for (int b = 0; b < 8; b++)
            xzv[b] = XZbuf[((size_t)(bglob0 + bbase + b) * T_STEPS + t) * G4 + j];

        // ---- phase 1: z1 = h1(t-1) @ U1 ----
        {
            u64 acc[8];
#pragma unroll
            for (int b = 0; b < 8; b++) acc[b] = 0ULL;
#pragma unroll 4
            for (int k4 = 0; k4 < 16; k4++) {
                ulonglong2 w = *(const ulonglong2*)&U1t[(k4 << 10) + (j << 2)];
#pragma unroll
                for (int b = 0; b < 8; b++) {
                    ulonglong2 h =
                        *(const ulonglong2*)&h1s[((cur << 4) + bbase + b) * HU + (k4 << 2)];
                    acc[b] = fma2(h.x, w.x, acc[b]);
                    acc[b] = fma2(h.y, w.y, acc[b]);
                }
            }
#pragma unroll
            for (int b = 0; b < 8; b++)
                zs[(bbase + b) * G4 + j] = hadd2(acc[b]) + xzv[b];
        }
        __syncthreads();

        // ---- phase 2: layer-1 state update ----
        {
            int b = bq;
            float zi = zs[b * G4 + uu];
            float zf = zs[b * G4 + uu + 64];
            float zg = zs[b * G4 + uu + 128];
            float zo = zs[b * G4 + uu + 192];
            c1a = sigf(zf) * c1a + sigf(zi) * tanhfast(zg);
            h1s[((nxt << 4) + b) * HU + uu] = sigf(zo) * tanhfast(c1a);
            b = bq + 8;
            zi = zs[b * G4 + uu];
            zf = zs[b * G4 + uu + 64];
            zg = zs[b * G4 + uu + 128];
            zo = zs[b * G4 + uu + 192];
            c1b = sigf(zf) * c1b + sigf(zi) * tanhfast(zg);
            h1s[((nxt << 4) + b) * HU + uu] = sigf(zo) * tanhfast(c1b);
        }
        __syncthreads();

        // ---- phase 3: z2 = h1(t) @ W2 + h2(t-1) @ U2 + b2 ----
        {
            u64 acc[8];
#pragma unroll
            for (int b = 0; b < 8; b++) acc[b] = 0ULL;
#pragma unroll 2
            for (int k4 = 0; k4 < 16; k4++) {
                ulonglong2 w2 = *(const ulonglong2*)&W2t[(k4 << 10) + (j << 2)];
                ulonglong2 u2 = *(const ulonglong2*)&U2t[(k4 << 10) + (j << 2)];
#pragma unroll
                for (int b = 0; b < 8; b++) {
                    ulonglong2 hn =
                        *(const ulonglong2*)&h1s[((nxt << 4) + bbase + b) * HU + (k4 << 2)];
                    ulonglong2 ho =
                        *(const ulonglong2*)&h2s[((cur << 4) + bbase + b) * HU + (k4 << 2)];
                    acc[b] = fma2(hn.x, w2.x, acc[b]);
                    acc[b] = fma2(hn.y, w2.y, acc[b]);
                    acc[b] = fma2(ho.x, u2.x, acc[b]);
                    acc[b] = fma2(ho.y, u2.y, acc[b]);
                }
            }
#pragma unroll
            for (int b = 0; b < 8; b++)
                zs[(bbase + b) * G4 + j] = hadd2(acc[b]) + b2j;
        }
        __syncthreads();

        // ---- phase 4: layer-2 state update ----
        {
            int b = bq;
            float zi = zs[b * G4 + uu];
            float zf = zs[b * G4 + uu + 64];
            float zg = zs[b * G4 + uu + 128];
            float zo = zs[b * G4 + uu + 192];
            c2a = sigf(zf) * c2a + sigf(zi) * tanhfast(zg);
            h2s[((nxt << 4) + b) * HU + uu] = sigf(zo) * tanhfast(c2a);
            b = bq + 8;
            zi = zs[b * G4 + uu];
            zf = zs[b * G4 + uu + 64];
            zg = zs[b * G4 + uu + 128];
            zo = zs[b * G4 + uu + 192];
            c2b = sigf(zf) * c2b + sigf(zi) * tanhfast(zg);
            h2s[((nxt << 4) + b) * HU + uu] = sigf(zo) * tanhfast(c2b);
        }
        __syncthreads();

        cur = nxt;
    }

    // final h2 is in parity 0 (cur == 0 after 256 flips)
    // ---- dense head 1: d = sigmoid(h2 @ Wd + bd), stored in zs ----
    {
        float bdv = bd[uu];
#pragma unroll 2
        for (int which = 0; which < 2; which++) {
            int b = bq + which * 8;
            float a = bdv;
#pragma unroll 4
            for (int k = 0; k < HU; k++)
                a += h2s[b * HU + k] * Wd[k * HU + uu];
            zs[b * HU + uu] = sigf(a);
        }
    }
    __syncthreads();
    // ---- dense head 2: out = sigmoid(d @ Wo + bo), one warp per batch row ----
    {
        const int b  = tid >> 5;
        const int ln = tid & 31;
        float p = zs[b * HU + ln] * Wo[ln] + zs[b * HU + ln + 32] * Wo[ln + 32];
#pragma unroll
        for (int s = 16; s; s >>= 1)
            p += __shfl_xor_sync(0xffffffffu, p, s);
        if (ln == 0)
            out[bglob0 + b] = sigf(p + bo[0]);
    }
}

extern "C" void kernel_launch(void* const* d_in, const int* in_sizes, int n_in,
                              void* d_out, int out_size)
{
    const float* x  = (const float*)d_in[0];
    const float* W1 = (const float*)d_in[1];
    const float* U1 = (const float*)d_in[2];
    const float* b1 = (const float*)d_in[3];
    const float* W2 = (const float*)d_in[4];
    const float* U2 = (const float*)d_in[5];
    const float* b2 = (const float*)d_in[6];
    const float* Wd = (const float*)d_in[7];
    const float* bd = (const float*)d_in[8];
    const float* Wo = (const float*)d_in[9];
    const float* bo = (const float*)d_in[10];
    float* out = (float*)d_out;

    // K1: xz prepass
    k1_xz<<<(BATCH * T_STEPS) / K1_BT, 256>>>(x, W1, b1);

    // K2: fused recurrence
    const size_t smem_bytes = (size_t)SM_TOTAL_FLOATS * sizeof(float);  // 229376
    cudaFuncSetAttribute(k2_main,
                         cudaFuncAttributeMaxDynamicSharedMemorySize,
                         (int)smem_bytes);
    k2_main<<<BATCH / BBK2, NTH, smem_bytes>>>(U1, W2, U2, b2, Wd, bd, Wo, bo, out);
}

// round 7
// speedup vs baseline: 2.2352x; 2.2352x over previous
#include <cuda_runtime.h>

#define HU      64
#define G4      256
#define T_STEPS 256
#define BATCH   4096
#define BB      32          // batch rows per K2 block
#define K2_NTH  256
#define K1_BT   128         // batch tile per K1 block
#define K1_NTH  256

typedef unsigned long long u64;

// 1 GB scratch: xz = x@W1 + b1, layout [t][j][b]  (b contiguous -> coalesced per-step loads)
__device__ float XZ[(size_t)T_STEPS * G4 * BATCH];

__device__ __forceinline__ u64 fma2(u64 a, u64 b, u64 c) {
    u64 d;
    asm("fma.rn.f32x2 %0, %1, %2, %3;" : "=l"(d) : "l"(a), "l"(b), "l"(c));
    return d;
}
__device__ __forceinline__ float hadd2(u64 v) {
    float l, h;
    asm("mov.b64 {%0, %1}, %2;" : "=f"(l), "=f"(h) : "l"(v));
    return l + h;
}
__device__ __forceinline__ float fexp(float x) {
    float y;
    asm("ex2.approx.f32 %0, %1;" : "=f"(y) : "f"(x * 1.4426950408889634f));
    return y;
}
__device__ __forceinline__ float frcp(float x) {
    float y;
    asm("rcp.approx.f32 %0, %1;" : "=f"(y) : "f"(x));
    return y;
}
__device__ __forceinline__ float sigf(float x) { return frcp(1.0f + fexp(-x)); }
__device__ __forceinline__ float tanhfast(float x) {
    return fmaf(2.0f, frcp(1.0f + fexp(-2.0f * x)), -1.0f);
}

// ===================== K1: xz prepass, writes [t][j][b] =====================
__global__ void __launch_bounds__(K1_NTH)
k1_xz(const float* __restrict__ x, const float* __restrict__ W1,
      const float* __restrict__ b1)
{
    extern __shared__ __align__(16) float sm1[];
    float* W1p = sm1;               // 8192 floats (k4-packed transpose)
    float* xs  = sm1 + 8192;        // 128 rows * 32 f

    const int tid = threadIdx.x;
    const int t   = blockIdx.y;
    const int b0  = blockIdx.x * K1_BT;

    for (int i = tid; i < 32 * G4; i += K1_NTH) {
        int f = i >> 8, j = i & 255;
        W1p[((f >> 2) << 10) + (j << 2) + (f & 3)] = W1[i];
    }
    for (int i = tid; i < K1_BT * 8; i += K1_NTH) {   // 1024 float4
        int row = i >> 3, f4 = i & 7;
        ((float4*)xs)[row * 8 + f4] =
            *(const float4*)(x + ((size_t)(b0 + row) * T_STEPS + t) * 32 + f4 * 4);
    }
    __syncthreads();

    const int u  = tid & 63;
    const int bg = tid >> 6;
    float bj[4];
#pragma unroll
    for (int jj = 0; jj < 4; jj++) bj[jj] = b1[u + 64 * jj];

    for (int rep = 0; rep < 4; rep++) {
        const int rb = bg * 32 + rep * 8;
        u64 acc[4][8];
#pragma unroll
        for (int jj = 0; jj < 4; jj++)
#pragma unroll
            for (int b = 0; b < 8; b++) acc[jj][b] = 0ULL;

#pragma unroll
        for (int f4 = 0; f4 < 8; f4++) {
            u64 w[4][2];
#pragma unroll
            for (int jj = 0; jj < 4; jj++) {
                ulonglong2 W = *(const ulonglong2*)&W1p[(f4 << 10) + ((u + 64 * jj) << 2)];
                w[jj][0] = W.x; w[jj][1] = W.y;
            }
#pragma unroll
            for (int b = 0; b < 8; b++) {
                ulonglong2 X = *(const ulonglong2*)&xs[(rb + b) * 32 + (f4 << 2)];
#pragma unroll
                for (int jj = 0; jj < 4; jj++) {
                    acc[jj][b] = fma2(X.x, w[jj][0], acc[jj][b]);
                    acc[jj][b] = fma2(X.y, w[jj][1], acc[jj][b]);
                }
            }
        }
#pragma unroll
        for (int jj = 0; jj < 4; jj++) {
            float z[8];
#pragma unroll
            for (int b = 0; b < 8; b++) z[b] = hadd2(acc[jj][b]) + bj[jj];
            float4* dst = (float4*)&XZ[((size_t)t * G4 + u + 64 * jj) * BATCH + b0 + rb];
            dst[0] = make_float4(z[0], z[1], z[2], z[3]);
            dst[1] = make_float4(z[4], z[5], z[6], z[7]);
        }
    }
}

// ===================== K2: fused 2-layer recurrence + dense heads =====================
// smem (floats): U1p @0 (16384), W2p @16384, U2p @32768  (k4-packed transposes)
//                h1 @49152 [2][32][64] (4096), h2 @53248 (4096)   -> 57344 floats = 224 KB
#define K2_SMF 57344

__global__ void __launch_bounds__(K2_NTH, 1)
k2_main(const float* __restrict__ U1, const float* __restrict__ W2,
        const float* __restrict__ U2, const float* __restrict__ b2,
        const float* __restrict__ Wd, const float* __restrict__ bd,
        const float* __restrict__ Wo, const float* __restrict__ bo,
        float* __restrict__ out)
{
    extern __shared__ __align__(16) float sm[];
    float* U1p = sm;
    float* W2p = sm + 16384;
    float* U2p = sm + 32768;
    float* h1s = sm + 49152;
    float* h2s = sm + 53248;

    const int tid = threadIdx.x;

    // load + k4-pack-transpose recurrent weights
    for (int i = tid; i < HU * G4; i += K2_NTH) {
        int k = i >> 8, j = i & 255;
        int d = ((k >> 2) << 10) + (j << 2) + (k & 3);
        float a = U1[i], b = W2[i], c = U2[i];
        U1p[d] = a; W2p[d] = b; U2p[d] = c;
    }
    // FIX (R3 bug): each state buffer is 4096 floats; previous loop ran to 8192
    // on h2s and wrote 16 KB past the smem allocation -> illegal memory access.
    for (int i = tid; i < 4096; i += K2_NTH) { h1s[i] = 0.0f; h2s[i] = 0.0f; }

    const int u   = tid & 63;      // hidden unit (gate column base)
    const int bg  = tid >> 6;      // row group (8 rows)
    const int b0g = bg * 8;
    const int bglob = blockIdx.x * BB;

    float b2j[4];
#pragma unroll
    for (int jj = 0; jj < 4; jj++) b2j[jj] = b2[u + 64 * jj];

    float c1[8], c2[8];
#pragma unroll
    for (int b = 0; b < 8; b++) { c1[b] = 0.0f; c2[b] = 0.0f; }

    __syncthreads();

    int cur = 0;
    for (int t = 0; t < T_STEPS; t++) {
        const int nxt = cur ^ 1;

        // ---------- phase 1: z1 = xz + h1(t-1) @ U1 ; update c1, h1 ----------
        {
            float4 xa[4], xb[4];
#pragma unroll
            for (int jj = 0; jj < 4; jj++) {
                const float* p = &XZ[((size_t)t * G4 + u + 64 * jj) * BATCH + bglob + b0g];
                xa[jj] = *(const float4*)p;
                xb[jj] = *(const float4*)(p + 4);
            }

            u64 acc[4][8];
#pragma unroll
            for (int jj = 0; jj < 4; jj++)
#pragma unroll
                for (int b = 0; b < 8; b++) acc[jj][b] = 0ULL;

#pragma unroll 4
            for (int k4 = 0; k4 < 16; k4++) {
                u64 w[4][2];
#pragma unroll
                for (int jj = 0; jj < 4; jj++) {
                    ulonglong2 W = *(const ulonglong2*)&U1p[(k4 << 10) + ((u + 64 * jj) << 2)];
                    w[jj][0] = W.x; w[jj][1] = W.y;
                }
#pragma unroll
                for (int b = 0; b < 8; b++) {
                    ulonglong2 H = *(const ulonglong2*)&h1s[((cur << 5) + b0g + b) * 64 + (k4 << 2)];
#pragma unroll
                    for (int jj = 0; jj < 4; jj++) {
                        acc[jj][b] = fma2(H.x, w[jj][0], acc[jj][b]);
                        acc[jj][b] = fma2(H.y, w[jj][1], acc[jj][b]);
                    }
                }
            }

            float z[4][8];
#pragma unroll
            for (int jj = 0; jj < 4; jj++) {
#pragma unroll
                for (int b = 0; b < 8; b++) z[jj][b] = hadd2(acc[jj][b]);
                z[jj][0] += xa[jj].x; z[jj][1] += xa[jj].y;
                z[jj][2] += xa[jj].z; z[jj][3] += xa[jj].w;
                z[jj][4] += xb[jj].x; z[jj][5] += xb[jj].y;
                z[jj][6] += xb[jj].z; z[jj][7] += xb[jj].w;
            }
#pragma unroll
            for (int b = 0; b < 8; b++) {
                c1[b] = sigf(z[1][b]) * c1[b] + sigf(z[0][b]) * tanhfast(z[2][b]);
                h1s[((nxt << 5) + b0g + b) * 64 + u] = sigf(z[3][b]) * tanhfast(c1[b]);
            }
        }
        __syncthreads();

        // ---------- phase 2: z2 = h1(t) @ W2 + h2(t-1) @ U2 + b2 ; update c2, h2 ----------
        {
            u64 acc[4][8];
#pragma unroll
            for (int jj = 0; jj < 4; jj++)
#pragma unroll
                for (int b = 0; b < 8; b++) acc[jj][b] = 0ULL;

#pragma unroll 2
            for (int k4 = 0; k4 < 16; k4++) {
                u64 w2[4][2], v2[4][2];
#pragma unroll
                for (int jj = 0; jj < 4; jj++) {
                    ulonglong2 W = *(const ulonglong2*)&W2p[(k4 << 10) + ((u + 64 * jj) << 2)];
                    w2[jj][0] = W.x; w2[jj][1] = W.y;
                    ulonglong2 V = *(const ulonglong2*)&U2p[(k4 << 10) + ((u + 64 * jj) << 2)];
                    v2[jj][0] = V.x; v2[jj][1] = V.y;
                }
#pragma unroll
                for (int b = 0; b < 8; b++) {
                    ulonglong2 Hn = *(const ulonglong2*)&h1s[((nxt << 5) + b0g + b) * 64 + (k4 << 2)];
                    ulonglong2 Ho = *(const ulonglong2*)&h2s[((cur << 5) + b0g + b) * 64 + (k4 << 2)];
#pragma unroll
                    for (int jj = 0; jj < 4; jj++) {
                        acc[jj][b] = fma2(Hn.x, w2[jj][0], acc[jj][b]);
                        acc[jj][b] = fma2(Hn.y, w2[jj][1], acc[jj][b]);
                        acc[jj][b] = fma2(Ho.x, v2[jj][0], acc[jj][b]);
                        acc[jj][b] = fma2(Ho.y, v2[jj][1], acc[jj][b]);
                    }
                }
            }

            float z[4][8];
#pragma unroll
            for (int jj = 0; jj < 4; jj++)
#pragma unroll
                for (int b = 0; b < 8; b++) z[jj][b] = hadd2(acc[jj][b]) + b2j[jj];
#pragma unroll
            for (int b = 0; b < 8; b++) {
                c2[b] = sigf(z[1][b]) * c2[b] + sigf(z[0][b]) * tanhfast(z[2][b]);
                h2s[((nxt << 5) + b0g + b) * 64 + u] = sigf(z[3][b]) * tanhfast(c2[b]);
            }
        }
        __syncthreads();

        cur = nxt;
    }

    // After 256 toggles cur == 0: final h2 lives in h2s[0..]
    // ---------- dense head 1: d = sigmoid(h2 @ Wd + bd) -> stash in h1s[0] ----------
    {
        const float bdv = bd[u];
#pragma unroll
        for (int b = 0; b < 8; b++) {
            float a = bdv;
#pragma unroll 8
            for (int k = 0; k < HU; k++)
                a += h2s[(b0g + b) * 64 + k] * Wd[k * HU + u];
            h1s[(b0g + b) * 64 + u] = sigf(a);
        }
    }
    __syncthreads();
    // ---------- dense head 2: out = sigmoid(d @ Wo + bo), warp per 4 rows ----------
    {
        const int w  = tid >> 5;
        const int ln = tid & 31;
        const float bov = bo[0];
        const float wo0 = Wo[ln], wo1 = Wo[ln + 32];
#pragma unroll
        for (int r = 0; r < 4; r++) {
            int row = w * 4 + r;
            float p = h1s[row * 64 + ln] * wo0 + h1s[row * 64 + ln + 32] * wo1;
#pragma unroll
            for (int s = 16; s; s >>= 1)
                p += __shfl_xor_sync(0xffffffffu, p, s);
            if (ln == 0)
                out[bglob + row] = sigf(p + bov);
        }
    }
}

extern "C" void kernel_launch(void* const* d_in, const int* in_sizes, int n_in,
                              void* d_out, int out_size)
{
    const float* x  = (const float*)d_in[0];
    const float* W1 = (const float*)d_in[1];
    const float* U1 = (const float*)d_in[2];
    const float* b1 = (const float*)d_in[3];
    const float* W2 = (const float*)d_in[4];
    const float* U2 = (const float*)d_in[5];
    const float* b2 = (const float*)d_in[6];
    const float* Wd = (const float*)d_in[7];
    const float* bd = (const float*)d_in[8];
    const float* Wo = (const float*)d_in[9];
    const float* bo = (const float*)d_in[10];
    float* out = (float*)d_out;

    // K1: xz prepass -> XZ[t][j][b]
    const size_t k1_smem = (8192 + K1_BT * 32) * sizeof(float);   // 48 KB
    cudaFuncSetAttribute(k1_xz, cudaFuncAttributeMaxDynamicSharedMemorySize, (int)k1_smem);
    dim3 g1(BATCH / K1_BT, T_STEPS);
    k1_xz<<<g1, K1_NTH, k1_smem>>>(x, W1, b1);

    // K2: fused recurrence
    const size_t k2_smem = (size_t)K2_SMF * sizeof(float);        // 229376 B
    cudaFuncSetAttribute(k2_main, cudaFuncAttributeMaxDynamicSharedMemorySize, (int)k2_smem);
    k2_main<<<BATCH / BB, K2_NTH, k2_smem>>>(U1, W2, U2, b2, Wd, bd, Wo, bo, out);
}